// round 2
// baseline (speedup 1.0000x reference)
#include <cuda_runtime.h>

#define NC 5
#define NR 14

__device__ __forceinline__ float fast_tanh(float x) {
    float r;
    asm("tanh.approx.f32 %0, %1;" : "=f"(r) : "f"(x));
    return r;
}

__global__ __launch_bounds__(256) void rnn_fused_kernel(
    const float* __restrict__ chem,   // [C, M*N]
    const float* __restrict__ mu,     // [R, M*N]
    const float* __restrict__ vu,     // [R, M*N]
    const float* __restrict__ Q,      // [C, 2R]
    const float* __restrict__ Ks,     // [C, C]
    const float* __restrict__ v,      // [1, C]
    const float* __restrict__ y,      // [C]
    const float* __restrict__ z,      // [C]
    const int*   __restrict__ tptr,   // scalar time_index
    float* __restrict__ out,          // [M*N]
    int quads)                        // M*N / 4
{
    // Uniform per-thread coefficient computation (no smem, no barrier).
    // All operands come via __ldg and are L1/const-cache resident.
    float invt = 1.0f / (float)__ldg(tptr);

    float sa[NC], sw[NC], sK[NC * NC];
    #pragma unroll
    for (int c = 0; c < NC; ++c) {
        float vc = __ldg(&v[c]);
        sa[c] = vc * __ldg(&y[c]);
        sw[c] = vc * __ldg(&z[c]);
    }
    #pragma unroll
    for (int c = 0; c < NC; ++c)
        #pragma unroll
        for (int d = 0; d < NC; ++d)
            sK[c * NC + d] = __ldg(&Ks[c * NC + d]);

    float sA[NR], sB[NR], sBp[NR];
    #pragma unroll
    for (int r = 0; r < NR; ++r) {
        float A = 0.0f, B = 0.0f;
        #pragma unroll
        for (int c = 0; c < NC; ++c) {
            A = fmaf(sw[c], __ldg(&Q[c * (2 * NR) + r]), A);
            B = fmaf(sw[c], __ldg(&Q[c * (2 * NR) + NR + r]), B);
        }
        sA[r] = A;
        sB[r] = B;
        sBp[r] = B * invt;
    }

    const float4* ch4 = (const float4*)chem;
    const float4* mu4 = (const float4*)mu;
    const float4* vu4 = (const float4*)vu;
    float4* out4 = (float4*)out;

    for (int i = blockIdx.x * blockDim.x + threadIdx.x; i < quads;
         i += gridDim.x * blockDim.x) {

        // ---- chemical part: a_c * chem_c + w_c * tanh(K @ chem) ----
        float chv[NC][4];
        #pragma unroll
        for (int c = 0; c < NC; ++c) {
            float4 t = ch4[c * quads + i];
            chv[c][0] = t.x; chv[c][1] = t.y; chv[c][2] = t.z; chv[c][3] = t.w;
        }

        float h[4] = {0.f, 0.f, 0.f, 0.f};
        #pragma unroll
        for (int c = 0; c < NC; ++c) {
            float ac = sa[c];
            float wc = sw[c];
            #pragma unroll
            for (int k = 0; k < 4; ++k) {
                float t = 0.f;
                #pragma unroll
                for (int d = 0; d < NC; ++d)
                    t = fmaf(sK[c * NC + d], chv[d][k], t);
                float th = fast_tanh(t);
                h[k] = fmaf(ac, chv[c][k], fmaf(wc, th, h[k]));
            }
        }

        // ---- update-rule part: A_r*mu + B'_r*vu - B_r*mu^2 ----
        #pragma unroll
        for (int r = 0; r < NR; ++r) {
            float4 m = mu4[r * quads + i];
            float4 u = vu4[r * quads + i];
            float Ar = sA[r], Br = sB[r], Bp = sBp[r];
            float mm[4] = {m.x, m.y, m.z, m.w};
            float uu[4] = {u.x, u.y, u.z, u.w};
            #pragma unroll
            for (int k = 0; k < 4; ++k) {
                // h += mu*(A - B*mu) + B'*vu
                h[k] = fmaf(mm[k], fmaf(-Br, mm[k], Ar),
                             fmaf(Bp, uu[k], h[k]));
            }
        }

        out4[i] = make_float4(h[0], h[1], h[2], h[3]);
    }
}

extern "C" void kernel_launch(void* const* d_in, const int* in_sizes, int n_in,
                              void* d_out, int out_size) {
    const float* chem = (const float*)d_in[0];
    const float* mu   = (const float*)d_in[1];
    const float* vu   = (const float*)d_in[2];
    const float* Q    = (const float*)d_in[3];
    const float* Ks   = (const float*)d_in[4];
    const float* v    = (const float*)d_in[5];
    const float* y    = (const float*)d_in[6];
    const float* z    = (const float*)d_in[7];
    const int*   t    = (const int*)d_in[8];
    float* out = (float*)d_out;

    int quads = out_size / 4;   // M*N / 4, M*N = 2048*1024
    int threads = 256;
    int blocks = (quads + threads - 1) / threads;

    rnn_fused_kernel<<<blocks, threads>>>(chem, mu, vu, Q, Ks, v, y, z, t,
                                          out, quads);
}

// round 3
// speedup vs baseline: 1.1526x; 1.1526x over previous
#include <cuda_runtime.h>

#define NC 5
#define NR 14

__device__ __forceinline__ float fast_tanh(float x) {
    float r;
    asm("tanh.approx.f32 %0, %1;" : "=f"(r) : "f"(x));
    return r;
}

__global__ __launch_bounds__(256, 4) void rnn_fused_kernel(
    const float* __restrict__ chem,   // [C, M*N]
    const float* __restrict__ mu,     // [R, M*N]
    const float* __restrict__ vu,     // [R, M*N]
    const float* __restrict__ Q,      // [C, 2R]
    const float* __restrict__ Ks,     // [C, C]
    const float* __restrict__ v,      // [1, C]
    const float* __restrict__ y,      // [C]
    const float* __restrict__ z,      // [C]
    const int*   __restrict__ tptr,   // scalar time_index
    float* __restrict__ out,          // [M*N]
    int quads)                        // M*N / 4
{
    // Uniform coefficient tables live in shared memory, NOT registers:
    // 67 floats of uniform state in regs was capping occupancy at 2 CTAs/SM.
    __shared__ float sA[NR], sB[NR], sBp[NR];
    __shared__ float sa[NC], sw[NC], sK[NC * NC];

    if (threadIdx.x == 0) {
        float invt = 1.0f / (float)(*tptr);
        float wreg[NC];
        #pragma unroll
        for (int c = 0; c < NC; ++c) {
            float vc = v[c];
            sa[c] = vc * y[c];
            wreg[c] = vc * z[c];
            sw[c] = wreg[c];
        }
        #pragma unroll
        for (int c = 0; c < NC; ++c)
            #pragma unroll
            for (int d = 0; d < NC; ++d)
                sK[c * NC + d] = Ks[c * NC + d];
        #pragma unroll
        for (int r = 0; r < NR; ++r) {
            float A = 0.0f, B = 0.0f;
            #pragma unroll
            for (int c = 0; c < NC; ++c) {
                A = fmaf(wreg[c], Q[c * (2 * NR) + r], A);
                B = fmaf(wreg[c], Q[c * (2 * NR) + NR + r], B);
            }
            sA[r] = A;
            sB[r] = B;
            sBp[r] = B * invt;
        }
    }
    __syncthreads();

    const float4* ch4 = (const float4*)chem;
    const float4* mu4 = (const float4*)mu;
    const float4* vu4 = (const float4*)vu;
    float4* out4 = (float4*)out;

    for (int i = blockIdx.x * blockDim.x + threadIdx.x; i < quads;
         i += gridDim.x * blockDim.x) {

        // ---- chemical part: a_c * chem_c + w_c * tanh(K @ chem) ----
        float chv[NC][4];
        #pragma unroll
        for (int c = 0; c < NC; ++c) {
            float4 t = ch4[c * quads + i];
            chv[c][0] = t.x; chv[c][1] = t.y; chv[c][2] = t.z; chv[c][3] = t.w;
        }

        float h[4] = {0.f, 0.f, 0.f, 0.f};
        #pragma unroll
        for (int c = 0; c < NC; ++c) {
            float ac = sa[c];
            float wc = sw[c];
            #pragma unroll
            for (int k = 0; k < 4; ++k) {
                float t = 0.f;
                #pragma unroll
                for (int d = 0; d < NC; ++d)
                    t = fmaf(sK[c * NC + d], chv[d][k], t);
                float th = fast_tanh(t);
                h[k] = fmaf(ac, chv[c][k], fmaf(wc, th, h[k]));
            }
        }

        // ---- update-rule part: A_r*mu + B'_r*vu - B_r*mu^2 ----
        #pragma unroll
        for (int r = 0; r < NR; ++r) {
            float4 m = mu4[r * quads + i];
            float4 u = vu4[r * quads + i];
            float Ar = sA[r], Br = sB[r], Bp = sBp[r];
            float mm[4] = {m.x, m.y, m.z, m.w};
            float uu[4] = {u.x, u.y, u.z, u.w};
            #pragma unroll
            for (int k = 0; k < 4; ++k) {
                // h += mu*(A - B*mu) + B'*vu
                h[k] = fmaf(mm[k], fmaf(-Br, mm[k], Ar),
                             fmaf(Bp, uu[k], h[k]));
            }
        }

        out4[i] = make_float4(h[0], h[1], h[2], h[3]);
    }
}

extern "C" void kernel_launch(void* const* d_in, const int* in_sizes, int n_in,
                              void* d_out, int out_size) {
    const float* chem = (const float*)d_in[0];
    const float* mu   = (const float*)d_in[1];
    const float* vu   = (const float*)d_in[2];
    const float* Q    = (const float*)d_in[3];
    const float* Ks   = (const float*)d_in[4];
    const float* v    = (const float*)d_in[5];
    const float* y    = (const float*)d_in[6];
    const float* z    = (const float*)d_in[7];
    const int*   t    = (const int*)d_in[8];
    float* out = (float*)d_out;

    int quads = out_size / 4;   // M*N / 4, M*N = 2048*1024
    int threads = 256;
    int blocks = (quads + threads - 1) / threads;

    rnn_fused_kernel<<<blocks, threads>>>(chem, mu, vu, Q, Ks, v, y, z, t,
                                          out, quads);
}

// round 4
// speedup vs baseline: 1.3054x; 1.1326x over previous
#include <cuda_runtime.h>

#define NC 5
#define NR 14

__device__ __forceinline__ float fast_tanh(float x) {
    float r;
    asm("tanh.approx.f32 %0, %1;" : "=f"(r) : "f"(x));
    return r;
}

__device__ __forceinline__ float4 ldcs4(const float4* p) {
    float4 r;
    asm("ld.global.cs.v4.f32 {%0,%1,%2,%3}, [%4];"
        : "=f"(r.x), "=f"(r.y), "=f"(r.z), "=f"(r.w) : "l"(p));
    return r;
}

__device__ __forceinline__ void stcs4(float4* p, float4 v) {
    asm("st.global.cs.v4.f32 [%0], {%1,%2,%3,%4};"
        :: "l"(p), "f"(v.x), "f"(v.y), "f"(v.z), "f"(v.w) : "memory");
}

__global__ __launch_bounds__(256, 5) void rnn_fused_kernel(
    const float* __restrict__ chem,   // [C, M*N]
    const float* __restrict__ mu,     // [R, M*N]
    const float* __restrict__ vu,     // [R, M*N]
    const float* __restrict__ Q,      // [C, 2R]
    const float* __restrict__ Ks,     // [C, C]
    const float* __restrict__ v,      // [1, C]
    const float* __restrict__ y,      // [C]
    const float* __restrict__ z,      // [C]
    const int*   __restrict__ tptr,   // scalar time_index
    float* __restrict__ out,          // [M*N]
    int quads)                        // M*N / 4
{
    // Uniform coefficient tables in shared memory (keeps them out of regs).
    __shared__ float sA[NR], sB[NR], sBp[NR];
    __shared__ float sa[NC], sw[NC], sK[NC * NC];

    if (threadIdx.x == 0) {
        float invt = 1.0f / (float)(*tptr);
        float wreg[NC];
        #pragma unroll
        for (int c = 0; c < NC; ++c) {
            float vc = v[c];
            sa[c] = vc * y[c];
            wreg[c] = vc * z[c];
            sw[c] = wreg[c];
        }
        #pragma unroll
        for (int c = 0; c < NC; ++c)
            #pragma unroll
            for (int d = 0; d < NC; ++d)
                sK[c * NC + d] = Ks[c * NC + d];
        #pragma unroll
        for (int r = 0; r < NR; ++r) {
            float A = 0.0f, B = 0.0f;
            #pragma unroll
            for (int c = 0; c < NC; ++c) {
                A = fmaf(wreg[c], Q[c * (2 * NR) + r], A);
                B = fmaf(wreg[c], Q[c * (2 * NR) + NR + r], B);
            }
            sA[r] = A;
            sB[r] = B;
            sBp[r] = B * invt;
        }
    }
    __syncthreads();

    const float4* ch4 = (const float4*)chem;
    const float4* mu4 = (const float4*)mu;
    const float4* vu4 = (const float4*)vu;
    float4* out4 = (float4*)out;

    const int stride = gridDim.x * blockDim.x;

    for (int i = blockIdx.x * blockDim.x + threadIdx.x; i < quads;
         i += stride) {

        float h[4] = {0.f, 0.f, 0.f, 0.f};

        // ---- update-rule part first (low register pressure, deep batching):
        //      h += mu*(A - B*mu) + B'*vu
        #pragma unroll
        for (int r = 0; r < NR; ++r) {
            float4 m = ldcs4(&mu4[r * quads + i]);
            float4 u = ldcs4(&vu4[r * quads + i]);
            float Ar = sA[r], Br = sB[r], Bp = sBp[r];
            float mm[4] = {m.x, m.y, m.z, m.w};
            float uu[4] = {u.x, u.y, u.z, u.w};
            #pragma unroll
            for (int k = 0; k < 4; ++k)
                h[k] = fmaf(mm[k], fmaf(-Br, mm[k], Ar),
                             fmaf(Bp, uu[k], h[k]));
        }

        // ---- chemical part: a_c * chem_c + w_c * tanh(K @ chem) ----
        float chv[NC][4];
        #pragma unroll
        for (int c = 0; c < NC; ++c) {
            float4 t = ldcs4(&ch4[c * quads + i]);
            chv[c][0] = t.x; chv[c][1] = t.y; chv[c][2] = t.z; chv[c][3] = t.w;
        }

        #pragma unroll
        for (int c = 0; c < NC; ++c) {
            float ac = sa[c];
            float wc = sw[c];
            #pragma unroll
            for (int k = 0; k < 4; ++k) {
                float t = 0.f;
                #pragma unroll
                for (int d = 0; d < NC; ++d)
                    t = fmaf(sK[c * NC + d], chv[d][k], t);
                float th = fast_tanh(t);
                h[k] = fmaf(ac, chv[c][k], fmaf(wc, th, h[k]));
            }
        }

        stcs4(&out4[i], make_float4(h[0], h[1], h[2], h[3]));
    }
}

extern "C" void kernel_launch(void* const* d_in, const int* in_sizes, int n_in,
                              void* d_out, int out_size) {
    const float* chem = (const float*)d_in[0];
    const float* mu   = (const float*)d_in[1];
    const float* vu   = (const float*)d_in[2];
    const float* Q    = (const float*)d_in[3];
    const float* Ks   = (const float*)d_in[4];
    const float* v    = (const float*)d_in[5];
    const float* y    = (const float*)d_in[6];
    const float* z    = (const float*)d_in[7];
    const int*   t    = (const int*)d_in[8];
    float* out = (float*)d_out;

    int quads = out_size / 4;   // M*N / 4
    int threads = 256;
    int blocks = (quads + threads - 1) / threads;
    int persistent = 152 * 5;   // GB300: 152 SMs x 5 CTAs/SM
    if (blocks > persistent) blocks = persistent;

    rnn_fused_kernel<<<blocks, threads>>>(chem, mu, vu, Q, Ks, v, y, z, t,
                                          out, quads);
}